// round 10
// baseline (speedup 1.0000x reference)
#include <cuda_runtime.h>
#include <math.h>

#define BB 16
#define SS 1024
#define NIN 7
#define NHID 28
#define HEADS 7
#define HD 4

// Scratch (device globals — no allocation allowed)
__device__ float g_Q [BB*HEADS*SS*HD];
__device__ float g_K [BB*HEADS*SS*HD];
__device__ float g_V [BB*HEADS*SS*HD];
__device__ float g_AO[BB*SS*NHID];
__device__ float g_Q2[BB*SS*NHID];
__device__ float g_K2[BB*SS*NHID];

// ---------------------------------------------------------------------------
// helpers
// ---------------------------------------------------------------------------
typedef unsigned long long u64;
__device__ __forceinline__ float ex2(float x) {            // single MUFU.EX2
    float r; asm("ex2.approx.ftz.f32 %0, %1;" : "=f"(r) : "f"(x)); return r;
}
__device__ __forceinline__ u64 pk2(float a, float b) {
    u64 r; asm("mov.b64 %0, {%1,%2};" : "=l"(r) : "f"(a), "f"(b)); return r;
}
__device__ __forceinline__ void up2(u64 v, float& a, float& b) {
    asm("mov.b64 {%0,%1}, %2;" : "=f"(a), "=f"(b) : "l"(v));
}
__device__ __forceinline__ u64 f2fma(u64 a, u64 b, u64 c) {
    u64 d; asm("fma.rn.f32x2 %0, %1, %2, %3;" : "=l"(d) : "l"(a), "l"(b), "l"(c)); return d;
}
__device__ __forceinline__ u64 f2mul(u64 a, u64 b) {
    u64 d; asm("mul.rn.f32x2 %0, %1, %2;" : "=l"(d) : "l"(a), "l"(b)); return d;
}
__device__ __forceinline__ u64 f2add(u64 a, u64 b) {
    u64 d; asm("add.rn.f32x2 %0, %1, %2;" : "=l"(d) : "l"(a), "l"(b)); return d;
}

// ---------------------------------------------------------------------------
// K1: QKV projection. 1 thread per (b,s) row. Q/K/V stored [B,H,S,4] (float4).
// ---------------------------------------------------------------------------
__global__ void k_qkv(const float* __restrict__ x,
                      const float* __restrict__ Wq, const float* __restrict__ bq,
                      const float* __restrict__ Wk, const float* __restrict__ bk,
                      const float* __restrict__ Wv, const float* __restrict__ bv) {
    __shared__ float sw[672];
    int tid = threadIdx.x;
    for (int i = tid; i < 196; i += blockDim.x) {
        sw[i] = Wq[i]; sw[224 + i] = Wk[i]; sw[448 + i] = Wv[i];
    }
    if (tid < 28) { sw[196 + tid] = bq[tid]; sw[420 + tid] = bk[tid]; sw[644 + tid] = bv[tid]; }
    __syncthreads();

    int r = blockIdx.x * blockDim.x + tid;        // 0..16383
    int b = r >> 10, s = r & 1023;

    float xv[7];
#pragma unroll
    for (int i = 0; i < 7; i++) xv[i] = x[r * 7 + i];

#pragma unroll
    for (int h = 0; h < 7; h++) {
        float qa[4], ka[4], va[4];
#pragma unroll
        for (int d = 0; d < 4; d++) {
            int j = h * 4 + d;
            float aq = sw[196 + j], ak = sw[420 + j], av = sw[644 + j];
#pragma unroll
            for (int i = 0; i < 7; i++) {
                float xi = xv[i];
                aq += xi * sw[i * 28 + j];
                ak += xi * sw[224 + i * 28 + j];
                av += xi * sw[448 + i * 28 + j];
            }
            qa[d] = aq; ka[d] = ak; va[d] = av;
        }
        int o = (b * 7 + h) * 1024 + s;
        reinterpret_cast<float4*>(g_Q)[o] = make_float4(qa[0], qa[1], qa[2], qa[3]);
        reinterpret_cast<float4*>(g_K)[o] = make_float4(ka[0], ka[1], ka[2], ka[3]);
        reinterpret_cast<float4*>(g_V)[o] = make_float4(va[0], va[1], va[2], va[3]);
    }
}

// ---------------------------------------------------------------------------
// K2: first attention — f32x2 packed over k-pairs, 4 k per iteration with
// two independent score chains and batched ex2 (MUFU latency amortized).
// Kt/Vt transposed-paired in smem (32KB); 1 q row/thread, grid 896.
// ---------------------------------------------------------------------------
__global__ void __launch_bounds__(128) k_attn1() {
    __shared__ ulonglong2 Kt[1024];
    __shared__ ulonglong2 Vt[1024];
    int b = blockIdx.z, h = blockIdx.y, chunk = blockIdx.x;   // chunk in [0,8)
    int bh = b * 7 + h;
    const float4* Kg = reinterpret_cast<const float4*>(g_K) + bh * 1024;
    const float4* Vg = reinterpret_cast<const float4*>(g_V) + bh * 1024;
    for (int p = threadIdx.x; p < 512; p += 128) {
        float4 a = Kg[2*p], c2 = Kg[2*p+1];
        Kt[2*p]   = make_ulonglong2(pk2(a.x, c2.x), pk2(a.y, c2.y));
        Kt[2*p+1] = make_ulonglong2(pk2(a.z, c2.z), pk2(a.w, c2.w));
        float4 va = Vg[2*p], vc = Vg[2*p+1];
        Vt[2*p]   = make_ulonglong2(pk2(va.x, vc.x), pk2(va.y, vc.y));
        Vt[2*p+1] = make_ulonglong2(pk2(va.z, vc.z), pk2(va.w, vc.w));
    }
    __syncthreads();

    int q = chunk * 128 + threadIdx.x;
    float4 qv = reinterpret_cast<const float4*>(g_Q)[bh * 1024 + q];
    const float c = 0.5f * 1.4426950408889634f;  // 1/sqrt(4) * log2(e)
    u64 qd0 = pk2(qv.x * c, qv.x * c);
    u64 qd1 = pk2(qv.y * c, qv.y * c);
    u64 qd2 = pk2(qv.z * c, qv.z * c);
    u64 qd3 = pk2(qv.w * c, qv.w * c);

    u64 acc0 = 0ull, acc1 = 0ull, acc2 = 0ull, acc3 = 0ull, l2 = 0ull;
#pragma unroll 2
    for (int p = 0; p < 256; p++) {               // 4 k per iter
        ulonglong2 k01a = Kt[4*p],   k01b = Kt[4*p+1];
        ulonglong2 k23a = Kt[4*p+2], k23b = Kt[4*p+3];
        u64 s01 = f2mul(qd0, k01a.x);
        u64 s23 = f2mul(qd0, k23a.x);
        s01 = f2fma(qd1, k01a.y, s01);  s23 = f2fma(qd1, k23a.y, s23);
        s01 = f2fma(qd2, k01b.x, s01);  s23 = f2fma(qd2, k23b.x, s23);
        s01 = f2fma(qd3, k01b.y, s01);  s23 = f2fma(qd3, k23b.y, s23);
        float sa, sb, sc, sd;
        up2(s01, sa, sb); up2(s23, sc, sd);
        float pa = ex2(sa), pb = ex2(sb), pc = ex2(sc), pd = ex2(sd);
        u64 p01 = pk2(pa, pb);
        u64 p23 = pk2(pc, pd);
        ulonglong2 v01a = Vt[4*p],   v01b = Vt[4*p+1];
        ulonglong2 v23a = Vt[4*p+2], v23b = Vt[4*p+3];
        acc0 = f2fma(p01, v01a.x, acc0);  acc1 = f2fma(p01, v01a.y, acc1);
        acc2 = f2fma(p01, v01b.x, acc2);  acc3 = f2fma(p01, v01b.y, acc3);
        acc0 = f2fma(p23, v23a.x, acc0);  acc1 = f2fma(p23, v23a.y, acc1);
        acc2 = f2fma(p23, v23b.x, acc2);  acc3 = f2fma(p23, v23b.y, acc3);
        l2 = f2add(l2, p01);
        l2 = f2add(l2, p23);
    }
    float le, lo; up2(l2, le, lo);
    float inv = 1.f / (le + lo);
    float e0,o0,e1,o1,e2,o2,e3,o3;
    up2(acc0, e0, o0); up2(acc1, e1, o1); up2(acc2, e2, o2); up2(acc3, e3, o3);
    *reinterpret_cast<float4*>(g_AO + ((b * 1024 + q) * 28 + h * 4)) =
        make_float4((e0+o0)*inv, (e1+o1)*inv, (e2+o2)*inv, (e3+o3)*inv);
}

// ---------------------------------------------------------------------------
// K3: LayerNorm(28) + FFN(28->7) + ReLU + residual -> out7 (d_out head),
// then Q2/K2 projections (7->28) into scratch. 1 thread per row.
// ---------------------------------------------------------------------------
__global__ void k_lnffn(const float* __restrict__ x,
                        const float* __restrict__ lnw, const float* __restrict__ lnb,
                        const float* __restrict__ W1,  const float* __restrict__ b1,
                        const float* __restrict__ Wq2, const float* __restrict__ bq2,
                        const float* __restrict__ Wk2, const float* __restrict__ bk2,
                        float* __restrict__ out7) {
    __shared__ float s_lnw[28], s_lnb[28], s_W1[196], s_b1[7];
    __shared__ float s_Wq2[196], s_bq2[28], s_Wk2[196], s_bk2[28];
    int tid = threadIdx.x;
    for (int i = tid; i < 196; i += blockDim.x) { s_W1[i] = W1[i]; s_Wq2[i] = Wq2[i]; s_Wk2[i] = Wk2[i]; }
    if (tid < 28) { s_lnw[tid] = lnw[tid]; s_lnb[tid] = lnb[tid]; s_bq2[tid] = bq2[tid]; s_bk2[tid] = bk2[tid]; }
    if (tid < 7)  { s_b1[tid] = b1[tid]; }
    __syncthreads();

    int r = blockIdx.x * blockDim.x + tid;
    float a[28];
    const float4* ap = reinterpret_cast<const float4*>(g_AO + r * 28);
#pragma unroll
    for (int i = 0; i < 7; i++) {
        float4 t = ap[i];
        a[4*i] = t.x; a[4*i+1] = t.y; a[4*i+2] = t.z; a[4*i+3] = t.w;
    }
    float mu = 0.f;
#pragma unroll
    for (int j = 0; j < 28; j++) mu += a[j];
    mu *= (1.f / 28.f);
    float var = 0.f;
#pragma unroll
    for (int j = 0; j < 28; j++) { float d = a[j] - mu; var += d * d; }
    var *= (1.f / 28.f);
    float rs = rsqrtf(var + 1e-5f);

    float y[28];
#pragma unroll
    for (int j = 0; j < 28; j++) y[j] = (a[j] - mu) * rs * s_lnw[j] + s_lnb[j];

    float z[7];
#pragma unroll
    for (int i = 0; i < 7; i++) {
        float t = s_b1[i];
#pragma unroll
        for (int j = 0; j < 28; j++) t += y[j] * s_W1[j * 7 + i];
        t = fmaxf(t, 0.f) + x[r * 7 + i];
        z[i] = t;
        out7[r * 7 + i] = t;
    }
#pragma unroll
    for (int j = 0; j < 28; j++) {
        float tq = s_bq2[j], tk = s_bk2[j];
#pragma unroll
        for (int i = 0; i < 7; i++) {
            tq += z[i] * s_Wq2[i * 28 + j];
            tk += z[i] * s_Wk2[i * 28 + j];
        }
        g_Q2[r * 28 + j] = tq;
        g_K2[r * 28 + j] = tk;
    }
}

// ---------------------------------------------------------------------------
// K4: second attention weights — SINGLE PASS. K2 rows {2m,2m+1} in registers;
// 16-q tiles; p kept in registers (pq[16]); split 7+7 FMA chains per dot;
// per-q warp-reduce overlaps next iter; one coalesced STG.64 write pass
// scaled by 1/sum. No gmem readback.
// ---------------------------------------------------------------------------
__global__ void __launch_bounds__(512, 1) k_attn2(float* __restrict__ out) {
    __shared__ float sQ[16 * 28];          // q tile (scaled)
    __shared__ float sPart[16][17];        // per-(q, warp) partial sums
    __shared__ float sInv[16];

    int b = blockIdx.y, tile = blockIdx.x;             // 64 tiles of 16 q rows
    int warp = threadIdx.x >> 5, lane = threadIdx.x & 31;
    const float SC2 = 1.4426950408889634f / 2.6457513110645906f; // log2(e)/sqrt(7)

    if (threadIdx.x < 448)
        sQ[threadIdx.x] = g_Q2[(b * 1024 + tile * 16) * 28 + threadIdx.x] * SC2;

    // This thread's two adjacent K2 rows -> registers
    int m = warp * 32 + lane;                           // 0..511
    ulonglong2 kA[7], kB[7];
    {
        const ulonglong2* a = reinterpret_cast<const ulonglong2*>(g_K2 + (b * 1024 + 2 * m) * 28);
        const ulonglong2* c = reinterpret_cast<const ulonglong2*>(g_K2 + (b * 1024 + 2 * m + 1) * 28);
#pragma unroll
        for (int j = 0; j < 7; j++) { kA[j] = a[j]; kB[j] = c[j]; }
    }
    __syncthreads();

    u64 pq[16];
#pragma unroll 2
    for (int q = 0; q < 16; q++) {
        const ulonglong2* qp = reinterpret_cast<const ulonglong2*>(sQ + q * 28);
        ulonglong2 qv[7];
#pragma unroll
        for (int j = 0; j < 7; j++) qv[j] = qp[j];      // broadcast LDS (N=1)

        // two split chains per dot (crit path 7 -> 4+3)
        u64 aL = f2mul(qv[0].x, kA[0].x);
        u64 aH = f2mul(qv[3].y, kA[3].y);
        u64 bL = f2mul(qv[0].x, kB[0].x);
        u64 bH = f2mul(qv[3].y, kB[3].y);
        aL = f2fma(qv[0].y, kA[0].y, aL);  bL = f2fma(qv[0].y, kB[0].y, bL);
        aH = f2fma(qv[4].x, kA[4].x, aH);  bH = f2fma(qv[4].x, kB[4].x, bH);
        aL = f2fma(qv[1].x, kA[1].x, aL);  bL = f2fma(qv[1].x, kB[1].x, bL);
        aH = f2fma(qv[4].y, kA[4].y, aH);  bH = f2fma(qv[4].y, kB[4].y, bH);
        aL = f2fma(qv[1].y, kA[1].y, aL);  bL = f2fma(qv[1].y, kB[1].y, bL);
        aH = f2fma(qv[5].x, kA[5].x, aH);  bH = f2fma(qv[5].x, kB[5].x, bH);
        aL = f2fma(qv[2].x, kA[2].x, aL);  bL = f2fma(qv[2].x, kB[2].x, bL);
        aH = f2fma(qv[5].y, kA[5].y, aH);  bH = f2fma(qv[5].y, kB[5].y, bH);
        aL = f2fma(qv[2].y, kA[2].y, aL);  bL = f2fma(qv[2].y, kB[2].y, bL);
        aH = f2fma(qv[6].x, kA[6].x, aH);  bH = f2fma(qv[6].x, kB[6].x, bH);
        aL = f2fma(qv[3].x, kA[3].x, aL);  bL = f2fma(qv[3].x, kB[3].x, bL);
        aH = f2fma(qv[6].y, kA[6].y, aH);  bH = f2fma(qv[6].y, kB[6].y, bH);
        u64 accA = f2add(aL, aH);
        u64 accB = f2add(bL, bH);

        float aLo, aHi, bLo, bHi;
        up2(accA, aLo, aHi); up2(accB, bLo, bHi);
        float pA = ex2(aLo + aHi);
        float pB = ex2(bLo + bHi);
        pq[q] = pk2(pA, pB);

        float s = pA + pB;
#pragma unroll
        for (int o = 16; o > 0; o >>= 1)
            s += __shfl_xor_sync(0xffffffffu, s, o);
        if (lane == 0) sPart[q][warp] = s;
    }
    __syncthreads();

    if (threadIdx.x < 16) {
        float s = 0.f;
#pragma unroll
        for (int w = 0; w < 16; w++) s += sPart[threadIdx.x][w];
        sInv[threadIdx.x] = 1.f / s;
    }
    __syncthreads();

    float* obase = out + (b * 1024 + tile * 16) * 1024;
#pragma unroll
    for (int q = 0; q < 16; q++) {
        float iv = sInv[q];
        float pA, pB; up2(pq[q], pA, pB);
        *reinterpret_cast<u64*>(&obase[q * 1024 + 2 * m]) = pk2(pA * iv, pB * iv);
    }
}

// ---------------------------------------------------------------------------
extern "C" void kernel_launch(void* const* d_in, const int* in_sizes, int n_in,
                              void* d_out, int out_size) {
    const float* x    = (const float*)d_in[0];
    const float* Wq   = (const float*)d_in[1];
    const float* bq   = (const float*)d_in[2];
    const float* Wk   = (const float*)d_in[3];
    const float* bk   = (const float*)d_in[4];
    const float* Wv   = (const float*)d_in[5];
    const float* bv   = (const float*)d_in[6];
    const float* lnw  = (const float*)d_in[7];
    const float* lnb  = (const float*)d_in[8];
    const float* W1   = (const float*)d_in[9];
    const float* b1   = (const float*)d_in[10];
    const float* Wq2  = (const float*)d_in[11];
    const float* bq2  = (const float*)d_in[12];
    const float* Wk2  = (const float*)d_in[13];
    const float* bk2  = (const float*)d_in[14];
    float* out = (float*)d_out;

    k_qkv<<<128, 128>>>(x, Wq, bq, Wk, bk, Wv, bv);
    k_attn1<<<dim3(8, 7, 16), 128>>>();
    k_lnffn<<<128, 128>>>(x, lnw, lnb, W1, b1, Wq2, bq2, Wk2, bk2, out);
    k_attn2<<<dim3(64, 16), 512>>>(out + BB * SS * NIN);
}

// round 11
// speedup vs baseline: 1.2652x; 1.2652x over previous
#include <cuda_runtime.h>
#include <math.h>

#define BB 16
#define SS 1024
#define NIN 7
#define NHID 28
#define HEADS 7
#define HD 4

// Scratch (device globals — no allocation allowed)
__device__ float g_Q [BB*HEADS*SS*HD];
__device__ float g_K [BB*HEADS*SS*HD];
__device__ float g_V [BB*HEADS*SS*HD];
__device__ float g_AO[BB*SS*NHID];
__device__ float g_Q2[BB*SS*NHID];
__device__ float g_K2[BB*SS*NHID];

// ---------------------------------------------------------------------------
// helpers
// ---------------------------------------------------------------------------
typedef unsigned long long u64;
__device__ __forceinline__ float ex2(float x) {            // single MUFU.EX2
    float r; asm("ex2.approx.ftz.f32 %0, %1;" : "=f"(r) : "f"(x)); return r;
}
__device__ __forceinline__ u64 pk2(float a, float b) {
    u64 r; asm("mov.b64 %0, {%1,%2};" : "=l"(r) : "f"(a), "f"(b)); return r;
}
__device__ __forceinline__ void up2(u64 v, float& a, float& b) {
    asm("mov.b64 {%0,%1}, %2;" : "=f"(a), "=f"(b) : "l"(v));
}
__device__ __forceinline__ u64 f2fma(u64 a, u64 b, u64 c) {
    u64 d; asm("fma.rn.f32x2 %0, %1, %2, %3;" : "=l"(d) : "l"(a), "l"(b), "l"(c)); return d;
}
__device__ __forceinline__ u64 f2mul(u64 a, u64 b) {
    u64 d; asm("mul.rn.f32x2 %0, %1, %2;" : "=l"(d) : "l"(a), "l"(b)); return d;
}
__device__ __forceinline__ u64 f2add(u64 a, u64 b) {
    u64 d; asm("add.rn.f32x2 %0, %1, %2;" : "=l"(d) : "l"(a), "l"(b)); return d;
}

// ---------------------------------------------------------------------------
// K1: QKV projection. 1 thread per (b,s) row. Q/K/V stored [B,H,S,4] (float4).
// ---------------------------------------------------------------------------
__global__ void k_qkv(const float* __restrict__ x,
                      const float* __restrict__ Wq, const float* __restrict__ bq,
                      const float* __restrict__ Wk, const float* __restrict__ bk,
                      const float* __restrict__ Wv, const float* __restrict__ bv) {
    __shared__ float sw[672];
    int tid = threadIdx.x;
    for (int i = tid; i < 196; i += blockDim.x) {
        sw[i] = Wq[i]; sw[224 + i] = Wk[i]; sw[448 + i] = Wv[i];
    }
    if (tid < 28) { sw[196 + tid] = bq[tid]; sw[420 + tid] = bk[tid]; sw[644 + tid] = bv[tid]; }
    __syncthreads();

    int r = blockIdx.x * blockDim.x + tid;        // 0..16383
    int b = r >> 10, s = r & 1023;

    float xv[7];
#pragma unroll
    for (int i = 0; i < 7; i++) xv[i] = x[r * 7 + i];

#pragma unroll
    for (int h = 0; h < 7; h++) {
        float qa[4], ka[4], va[4];
#pragma unroll
        for (int d = 0; d < 4; d++) {
            int j = h * 4 + d;
            float aq = sw[196 + j], ak = sw[420 + j], av = sw[644 + j];
#pragma unroll
            for (int i = 0; i < 7; i++) {
                float xi = xv[i];
                aq += xi * sw[i * 28 + j];
                ak += xi * sw[224 + i * 28 + j];
                av += xi * sw[448 + i * 28 + j];
            }
            qa[d] = aq; ka[d] = ak; va[d] = av;
        }
        int o = (b * 7 + h) * 1024 + s;
        reinterpret_cast<float4*>(g_Q)[o] = make_float4(qa[0], qa[1], qa[2], qa[3]);
        reinterpret_cast<float4*>(g_K)[o] = make_float4(ka[0], ka[1], ka[2], ka[3]);
        reinterpret_cast<float4*>(g_V)[o] = make_float4(va[0], va[1], va[2], va[3]);
    }
}

// ---------------------------------------------------------------------------
// K2: first attention — 2 q rows per thread over k-PAIR packing.
// Kt/Vt transposed-paired in smem (32KB, no duplication); every LDS serves
// both q rows. Per (2q,2k): 4 LDS + 18 FMA-pipe + 4 MUFU (MUFU at capacity,
// LSU at half capacity — the slack R9 lacked). Grid (4,7,16)=448, 7 CTA/SM.
// ---------------------------------------------------------------------------
__global__ void __launch_bounds__(128) k_attn1() {
    __shared__ ulonglong2 Kt[1024];
    __shared__ ulonglong2 Vt[1024];
    int b = blockIdx.z, h = blockIdx.y, chunk = blockIdx.x;   // chunk in [0,4)
    int bh = b * 7 + h;
    const float4* Kg = reinterpret_cast<const float4*>(g_K) + bh * 1024;
    const float4* Vg = reinterpret_cast<const float4*>(g_V) + bh * 1024;
    for (int p = threadIdx.x; p < 512; p += 128) {
        float4 a = Kg[2*p], c2 = Kg[2*p+1];
        Kt[2*p]   = make_ulonglong2(pk2(a.x, c2.x), pk2(a.y, c2.y));
        Kt[2*p+1] = make_ulonglong2(pk2(a.z, c2.z), pk2(a.w, c2.w));
        float4 va = Vg[2*p], vc = Vg[2*p+1];
        Vt[2*p]   = make_ulonglong2(pk2(va.x, vc.x), pk2(va.y, vc.y));
        Vt[2*p+1] = make_ulonglong2(pk2(va.z, vc.z), pk2(va.w, vc.w));
    }
    __syncthreads();

    int qA = chunk * 256 + threadIdx.x;           // rows qA, qA+128
    const float c = 0.5f * 1.4426950408889634f;   // 1/sqrt(4) * log2(e)
    float4 q0 = reinterpret_cast<const float4*>(g_Q)[bh * 1024 + qA];
    float4 q1 = reinterpret_cast<const float4*>(g_Q)[bh * 1024 + qA + 128];
    u64 q0d0 = pk2(q0.x * c, q0.x * c), q0d1 = pk2(q0.y * c, q0.y * c);
    u64 q0d2 = pk2(q0.z * c, q0.z * c), q0d3 = pk2(q0.w * c, q0.w * c);
    u64 q1d0 = pk2(q1.x * c, q1.x * c), q1d1 = pk2(q1.y * c, q1.y * c);
    u64 q1d2 = pk2(q1.z * c, q1.z * c), q1d3 = pk2(q1.w * c, q1.w * c);

    u64 a00 = 0ull, a01 = 0ull, a02 = 0ull, a03 = 0ull, l0 = 0ull;
    u64 a10 = 0ull, a11 = 0ull, a12 = 0ull, a13 = 0ull, l1 = 0ull;
#pragma unroll 4
    for (int p = 0; p < 512; p++) {
        ulonglong2 k01 = Kt[2*p];
        ulonglong2 k23 = Kt[2*p+1];
        u64 s0 = f2mul(q0d0, k01.x);
        u64 s1 = f2mul(q1d0, k01.x);
        s0 = f2fma(q0d1, k01.y, s0);  s1 = f2fma(q1d1, k01.y, s1);
        s0 = f2fma(q0d2, k23.x, s0);  s1 = f2fma(q1d2, k23.x, s1);
        s0 = f2fma(q0d3, k23.y, s0);  s1 = f2fma(q1d3, k23.y, s1);
        float sa, sb, sc, sd;
        up2(s0, sa, sb); up2(s1, sc, sd);
        u64 p0 = pk2(ex2(sa), ex2(sb));
        u64 p1 = pk2(ex2(sc), ex2(sd));
        ulonglong2 v01 = Vt[2*p];
        ulonglong2 v23 = Vt[2*p+1];
        a00 = f2fma(p0, v01.x, a00);  a10 = f2fma(p1, v01.x, a10);
        a01 = f2fma(p0, v01.y, a01);  a11 = f2fma(p1, v01.y, a11);
        a02 = f2fma(p0, v23.x, a02);  a12 = f2fma(p1, v23.x, a12);
        a03 = f2fma(p0, v23.y, a03);  a13 = f2fma(p1, v23.y, a13);
        l0 = f2add(l0, p0);           l1 = f2add(l1, p1);
    }
    {
        float le, lo; up2(l0, le, lo);
        float inv = 1.f / (le + lo);
        float e0,o0,e1,o1,e2,o2,e3,o3;
        up2(a00, e0, o0); up2(a01, e1, o1); up2(a02, e2, o2); up2(a03, e3, o3);
        *reinterpret_cast<float4*>(g_AO + ((b * 1024 + qA) * 28 + h * 4)) =
            make_float4((e0+o0)*inv, (e1+o1)*inv, (e2+o2)*inv, (e3+o3)*inv);
    }
    {
        float le, lo; up2(l1, le, lo);
        float inv = 1.f / (le + lo);
        float e0,o0,e1,o1,e2,o2,e3,o3;
        up2(a10, e0, o0); up2(a11, e1, o1); up2(a12, e2, o2); up2(a13, e3, o3);
        *reinterpret_cast<float4*>(g_AO + ((b * 1024 + qA + 128) * 28 + h * 4)) =
            make_float4((e0+o0)*inv, (e1+o1)*inv, (e2+o2)*inv, (e3+o3)*inv);
    }
}

// ---------------------------------------------------------------------------
// K3: LayerNorm(28) + FFN(28->7) + ReLU + residual -> out7 (d_out head),
// then Q2/K2 projections (7->28) into scratch. 1 thread per row.
// ---------------------------------------------------------------------------
__global__ void k_lnffn(const float* __restrict__ x,
                        const float* __restrict__ lnw, const float* __restrict__ lnb,
                        const float* __restrict__ W1,  const float* __restrict__ b1,
                        const float* __restrict__ Wq2, const float* __restrict__ bq2,
                        const float* __restrict__ Wk2, const float* __restrict__ bk2,
                        float* __restrict__ out7) {
    __shared__ float s_lnw[28], s_lnb[28], s_W1[196], s_b1[7];
    __shared__ float s_Wq2[196], s_bq2[28], s_Wk2[196], s_bk2[28];
    int tid = threadIdx.x;
    for (int i = tid; i < 196; i += blockDim.x) { s_W1[i] = W1[i]; s_Wq2[i] = Wq2[i]; s_Wk2[i] = Wk2[i]; }
    if (tid < 28) { s_lnw[tid] = lnw[tid]; s_lnb[tid] = lnb[tid]; s_bq2[tid] = bq2[tid]; s_bk2[tid] = bk2[tid]; }
    if (tid < 7)  { s_b1[tid] = b1[tid]; }
    __syncthreads();

    int r = blockIdx.x * blockDim.x + tid;
    float a[28];
    const float4* ap = reinterpret_cast<const float4*>(g_AO + r * 28);
#pragma unroll
    for (int i = 0; i < 7; i++) {
        float4 t = ap[i];
        a[4*i] = t.x; a[4*i+1] = t.y; a[4*i+2] = t.z; a[4*i+3] = t.w;
    }
    float mu = 0.f;
#pragma unroll
    for (int j = 0; j < 28; j++) mu += a[j];
    mu *= (1.f / 28.f);
    float var = 0.f;
#pragma unroll
    for (int j = 0; j < 28; j++) { float d = a[j] - mu; var += d * d; }
    var *= (1.f / 28.f);
    float rs = rsqrtf(var + 1e-5f);

    float y[28];
#pragma unroll
    for (int j = 0; j < 28; j++) y[j] = (a[j] - mu) * rs * s_lnw[j] + s_lnb[j];

    float z[7];
#pragma unroll
    for (int i = 0; i < 7; i++) {
        float t = s_b1[i];
#pragma unroll
        for (int j = 0; j < 28; j++) t += y[j] * s_W1[j * 7 + i];
        t = fmaxf(t, 0.f) + x[r * 7 + i];
        z[i] = t;
        out7[r * 7 + i] = t;
    }
#pragma unroll
    for (int j = 0; j < 28; j++) {
        float tq = s_bq2[j], tk = s_bk2[j];
#pragma unroll
        for (int i = 0; i < 7; i++) {
            tq += z[i] * s_Wq2[i * 28 + j];
            tk += z[i] * s_Wk2[i * 28 + j];
        }
        g_Q2[r * 28 + j] = tq;
        g_K2[r * 28 + j] = tk;
    }
}

// ---------------------------------------------------------------------------
// K4: second attention weights — K2 in registers, Q2 broadcast from smem.
// (Reverted to the R8 two-pass version: 47.4us measured.)
// Block = 512 thr (16 warps). Thread owns ADJACENT k rows {2m, 2m+1}
// so (pA,pB) packs into one STG.64. Row sums in the normalize pass, where
// each warp owns 2 whole q-rows (8 LDG.128/lane, sum, 5 shfl, 8 STG.128).
// ---------------------------------------------------------------------------
__global__ void __launch_bounds__(512, 1) k_attn2(float* __restrict__ out) {
    __shared__ float sQ[32 * 28];          // q tile (scaled)

    int b = blockIdx.y, tile = blockIdx.x;             // 32 tiles of 32 q rows
    int warp = threadIdx.x >> 5, lane = threadIdx.x & 31;
    const float SC2 = 1.4426950408889634f / 2.6457513110645906f; // log2(e)/sqrt(7)

    for (int t = threadIdx.x; t < 32 * 28; t += 512)
        sQ[t] = g_Q2[(b * 1024 + tile * 32) * 28 + t] * SC2;

    int m = warp * 32 + lane;                           // 0..511
    ulonglong2 kA[7], kB[7];
    {
        const ulonglong2* a = reinterpret_cast<const ulonglong2*>(g_K2 + (b * 1024 + 2 * m) * 28);
        const ulonglong2* c = reinterpret_cast<const ulonglong2*>(g_K2 + (b * 1024 + 2 * m + 1) * 28);
#pragma unroll
        for (int j = 0; j < 7; j++) { kA[j] = a[j]; kB[j] = c[j]; }
    }
    __syncthreads();

    float* obase = out + (b * 1024 + tile * 32) * 1024;

#pragma unroll 2
    for (int q = 0; q < 32; q++) {
        const ulonglong2* qp = reinterpret_cast<const ulonglong2*>(sQ + q * 28);
        ulonglong2 qv[7];
#pragma unroll
        for (int j = 0; j < 7; j++) qv[j] = qp[j];      // broadcast LDS (N=1)

        u64 accA = f2mul(qv[0].x, kA[0].x);
        u64 accB = f2mul(qv[0].x, kB[0].x);
        accA = f2fma(qv[0].y, kA[0].y, accA);  accB = f2fma(qv[0].y, kB[0].y, accB);
        accA = f2fma(qv[1].x, kA[1].x, accA);  accB = f2fma(qv[1].x, kB[1].x, accB);
        accA = f2fma(qv[1].y, kA[1].y, accA);  accB = f2fma(qv[1].y, kB[1].y, accB);
        accA = f2fma(qv[2].x, kA[2].x, accA);  accB = f2fma(qv[2].x, kB[2].x, accB);
        accA = f2fma(qv[2].y, kA[2].y, accA);  accB = f2fma(qv[2].y, kB[2].y, accB);
        accA = f2fma(qv[3].x, kA[3].x, accA);  accB = f2fma(qv[3].x, kB[3].x, accB);
        accA = f2fma(qv[3].y, kA[3].y, accA);  accB = f2fma(qv[3].y, kB[3].y, accB);
        accA = f2fma(qv[4].x, kA[4].x, accA);  accB = f2fma(qv[4].x, kB[4].x, accB);
        accA = f2fma(qv[4].y, kA[4].y, accA);  accB = f2fma(qv[4].y, kB[4].y, accB);
        accA = f2fma(qv[5].x, kA[5].x, accA);  accB = f2fma(qv[5].x, kB[5].x, accB);
        accA = f2fma(qv[5].y, kA[5].y, accA);  accB = f2fma(qv[5].y, kB[5].y, accB);
        accA = f2fma(qv[6].x, kA[6].x, accA);  accB = f2fma(qv[6].x, kB[6].x, accB);
        accA = f2fma(qv[6].y, kA[6].y, accA);  accB = f2fma(qv[6].y, kB[6].y, accB);

        float aLo, aHi, bLo, bHi;
        up2(accA, aLo, aHi); up2(accB, bLo, bHi);
        float pA = ex2(aLo + aHi);
        float pB = ex2(bLo + bHi);

        *reinterpret_cast<u64*>(&obase[q * 1024 + 2 * m]) = pk2(pA, pB);
    }
    __syncthreads();   // make all warps' global p-writes visible block-wide

    // Normalize pass: each warp owns q-rows {warp, warp+16}.
#pragma unroll
    for (int rr = 0; rr < 2; rr++) {
        int q = warp + rr * 16;
        float4* row = reinterpret_cast<float4*>(obase + q * 1024);
        float4 v[8];
#pragma unroll
        for (int i = 0; i < 8; i++) v[i] = row[i * 32 + lane];
        float s = 0.f;
#pragma unroll
        for (int i = 0; i < 8; i++) s += (v[i].x + v[i].y) + (v[i].z + v[i].w);
#pragma unroll
        for (int o = 16; o > 0; o >>= 1)
            s += __shfl_xor_sync(0xffffffffu, s, o);
        float iv = 1.f / s;
#pragma unroll
        for (int i = 0; i < 8; i++) {
            v[i].x *= iv; v[i].y *= iv; v[i].z *= iv; v[i].w *= iv;
            row[i * 32 + lane] = v[i];
        }
    }
}

// ---------------------------------------------------------------------------
extern "C" void kernel_launch(void* const* d_in, const int* in_sizes, int n_in,
                              void* d_out, int out_size) {
    const float* x    = (const float*)d_in[0];
    const float* Wq   = (const float*)d_in[1];
    const float* bq   = (const float*)d_in[2];
    const float* Wk   = (const float*)d_in[3];
    const float* bk   = (const float*)d_in[4];
    const float* Wv   = (const float*)d_in[5];
    const float* bv   = (const float*)d_in[6];
    const float* lnw  = (const float*)d_in[7];
    const float* lnb  = (const float*)d_in[8];
    const float* W1   = (const float*)d_in[9];
    const float* b1   = (const float*)d_in[10];
    const float* Wq2  = (const float*)d_in[11];
    const float* bq2  = (const float*)d_in[12];
    const float* Wk2  = (const float*)d_in[13];
    const float* bk2  = (const float*)d_in[14];
    float* out = (float*)d_out;

    k_qkv<<<128, 128>>>(x, Wq, bq, Wk, bk, Wv, bv);
    k_attn1<<<dim3(4, 7, 16), 128>>>();
    k_lnffn<<<128, 128>>>(x, lnw, lnb, W1, b1, Wq2, bq2, Wk2, bk2, out);
    k_attn2<<<dim3(32, 16), 512>>>(out + BB * SS * NIN);
}

// round 12
// speedup vs baseline: 1.2664x; 1.0009x over previous
#include <cuda_runtime.h>
#include <math.h>

#define BB 16
#define SS 1024
#define NIN 7
#define NHID 28
#define HEADS 7
#define HD 4

// Scratch (device globals — no allocation allowed)
__device__ float g_Q [BB*HEADS*SS*HD];
__device__ float g_K [BB*HEADS*SS*HD];
__device__ float g_V [BB*HEADS*SS*HD];
__device__ float g_AO[BB*SS*NHID];
__device__ float g_Q2[BB*SS*NHID];
__device__ float g_K2[BB*SS*NHID];

// ---------------------------------------------------------------------------
// helpers
// ---------------------------------------------------------------------------
typedef unsigned long long u64;
__device__ __forceinline__ float ex2(float x) {            // single MUFU.EX2
    float r; asm("ex2.approx.ftz.f32 %0, %1;" : "=f"(r) : "f"(x)); return r;
}
__device__ __forceinline__ u64 pk2(float a, float b) {
    u64 r; asm("mov.b64 %0, {%1,%2};" : "=l"(r) : "f"(a), "f"(b)); return r;
}
__device__ __forceinline__ void up2(u64 v, float& a, float& b) {
    asm("mov.b64 {%0,%1}, %2;" : "=f"(a), "=f"(b) : "l"(v));
}
__device__ __forceinline__ u64 f2fma(u64 a, u64 b, u64 c) {
    u64 d; asm("fma.rn.f32x2 %0, %1, %2, %3;" : "=l"(d) : "l"(a), "l"(b), "l"(c)); return d;
}
__device__ __forceinline__ u64 f2mul(u64 a, u64 b) {
    u64 d; asm("mul.rn.f32x2 %0, %1, %2;" : "=l"(d) : "l"(a), "l"(b)); return d;
}
__device__ __forceinline__ u64 f2add(u64 a, u64 b) {
    u64 d; asm("add.rn.f32x2 %0, %1, %2;" : "=l"(d) : "l"(a), "l"(b)); return d;
}

// ---------------------------------------------------------------------------
// K1: QKV projection. 1 thread per (b,s) row. Q/K/V stored [B,H,S,4] (float4).
// ---------------------------------------------------------------------------
__global__ void k_qkv(const float* __restrict__ x,
                      const float* __restrict__ Wq, const float* __restrict__ bq,
                      const float* __restrict__ Wk, const float* __restrict__ bk,
                      const float* __restrict__ Wv, const float* __restrict__ bv) {
    __shared__ float sw[672];
    int tid = threadIdx.x;
    for (int i = tid; i < 196; i += blockDim.x) {
        sw[i] = Wq[i]; sw[224 + i] = Wk[i]; sw[448 + i] = Wv[i];
    }
    if (tid < 28) { sw[196 + tid] = bq[tid]; sw[420 + tid] = bk[tid]; sw[644 + tid] = bv[tid]; }
    __syncthreads();

    int r = blockIdx.x * blockDim.x + tid;        // 0..16383
    int b = r >> 10, s = r & 1023;

    float xv[7];
#pragma unroll
    for (int i = 0; i < 7; i++) xv[i] = x[r * 7 + i];

#pragma unroll
    for (int h = 0; h < 7; h++) {
        float qa[4], ka[4], va[4];
#pragma unroll
        for (int d = 0; d < 4; d++) {
            int j = h * 4 + d;
            float aq = sw[196 + j], ak = sw[420 + j], av = sw[644 + j];
#pragma unroll
            for (int i = 0; i < 7; i++) {
                float xi = xv[i];
                aq += xi * sw[i * 28 + j];
                ak += xi * sw[224 + i * 28 + j];
                av += xi * sw[448 + i * 28 + j];
            }
            qa[d] = aq; ka[d] = ak; va[d] = av;
        }
        int o = (b * 7 + h) * 1024 + s;
        reinterpret_cast<float4*>(g_Q)[o] = make_float4(qa[0], qa[1], qa[2], qa[3]);
        reinterpret_cast<float4*>(g_K)[o] = make_float4(ka[0], ka[1], ka[2], ka[3]);
        reinterpret_cast<float4*>(g_V)[o] = make_float4(va[0], va[1], va[2], va[3]);
    }
}

// ---------------------------------------------------------------------------
// K2: first attention — 2 q rows x 4 k per iteration, f32x2 over k-pairs.
// Kt/Vt transposed-paired in smem (32KB). 4 independent score chains,
// 8 ex2 batched back-to-back (MUFU latency amortized).
// Grid (4,7,16)=448, 128 thr.
// ---------------------------------------------------------------------------
__global__ void __launch_bounds__(128) k_attn1() {
    __shared__ ulonglong2 Kt[1024];
    __shared__ ulonglong2 Vt[1024];
    int b = blockIdx.z, h = blockIdx.y, chunk = blockIdx.x;   // chunk in [0,4)
    int bh = b * 7 + h;
    const float4* Kg = reinterpret_cast<const float4*>(g_K) + bh * 1024;
    const float4* Vg = reinterpret_cast<const float4*>(g_V) + bh * 1024;
    for (int p = threadIdx.x; p < 512; p += 128) {
        float4 a = Kg[2*p], c2 = Kg[2*p+1];
        Kt[2*p]   = make_ulonglong2(pk2(a.x, c2.x), pk2(a.y, c2.y));
        Kt[2*p+1] = make_ulonglong2(pk2(a.z, c2.z), pk2(a.w, c2.w));
        float4 va = Vg[2*p], vc = Vg[2*p+1];
        Vt[2*p]   = make_ulonglong2(pk2(va.x, vc.x), pk2(va.y, vc.y));
        Vt[2*p+1] = make_ulonglong2(pk2(va.z, vc.z), pk2(va.w, vc.w));
    }
    __syncthreads();

    int qA = chunk * 256 + threadIdx.x;           // rows qA, qA+128
    const float c = 0.5f * 1.4426950408889634f;   // 1/sqrt(4) * log2(e)
    float4 q0 = reinterpret_cast<const float4*>(g_Q)[bh * 1024 + qA];
    float4 q1 = reinterpret_cast<const float4*>(g_Q)[bh * 1024 + qA + 128];
    u64 q0d0 = pk2(q0.x * c, q0.x * c), q0d1 = pk2(q0.y * c, q0.y * c);
    u64 q0d2 = pk2(q0.z * c, q0.z * c), q0d3 = pk2(q0.w * c, q0.w * c);
    u64 q1d0 = pk2(q1.x * c, q1.x * c), q1d1 = pk2(q1.y * c, q1.y * c);
    u64 q1d2 = pk2(q1.z * c, q1.z * c), q1d3 = pk2(q1.w * c, q1.w * c);

    u64 a00 = 0ull, a01 = 0ull, a02 = 0ull, a03 = 0ull, l0 = 0ull;
    u64 a10 = 0ull, a11 = 0ull, a12 = 0ull, a13 = 0ull, l1 = 0ull;
#pragma unroll 2
    for (int p = 0; p < 256; p++) {               // 4 k (2 pairs) per iter
        ulonglong2 kA01 = Kt[4*p],   kA23 = Kt[4*p+1];   // pair a = k(4p..4p+1)
        ulonglong2 kB01 = Kt[4*p+2], kB23 = Kt[4*p+3];   // pair b = k(4p+2..4p+3)
        u64 s0a = f2mul(q0d0, kA01.x);
        u64 s0b = f2mul(q0d0, kB01.x);
        u64 s1a = f2mul(q1d0, kA01.x);
        u64 s1b = f2mul(q1d0, kB01.x);
        s0a = f2fma(q0d1, kA01.y, s0a);  s0b = f2fma(q0d1, kB01.y, s0b);
        s1a = f2fma(q1d1, kA01.y, s1a);  s1b = f2fma(q1d1, kB01.y, s1b);
        s0a = f2fma(q0d2, kA23.x, s0a);  s0b = f2fma(q0d2, kB23.x, s0b);
        s1a = f2fma(q1d2, kA23.x, s1a);  s1b = f2fma(q1d2, kB23.x, s1b);
        s0a = f2fma(q0d3, kA23.y, s0a);  s0b = f2fma(q0d3, kB23.y, s0b);
        s1a = f2fma(q1d3, kA23.y, s1a);  s1b = f2fma(q1d3, kB23.y, s1b);
        float w0,w1,w2,w3,w4,w5,w6,w7;
        up2(s0a, w0, w1); up2(s0b, w2, w3);
        up2(s1a, w4, w5); up2(s1b, w6, w7);
        float e0 = ex2(w0), e1 = ex2(w1), e2 = ex2(w2), e3 = ex2(w3);
        float e4 = ex2(w4), e5 = ex2(w5), e6 = ex2(w6), e7 = ex2(w7);
        u64 p0a = pk2(e0, e1), p0b = pk2(e2, e3);
        u64 p1a = pk2(e4, e5), p1b = pk2(e6, e7);
        ulonglong2 vA01 = Vt[4*p],   vA23 = Vt[4*p+1];
        ulonglong2 vB01 = Vt[4*p+2], vB23 = Vt[4*p+3];
        a00 = f2fma(p0a, vA01.x, a00);  a10 = f2fma(p1a, vA01.x, a10);
        a01 = f2fma(p0a, vA01.y, a01);  a11 = f2fma(p1a, vA01.y, a11);
        a02 = f2fma(p0a, vA23.x, a02);  a12 = f2fma(p1a, vA23.x, a12);
        a03 = f2fma(p0a, vA23.y, a03);  a13 = f2fma(p1a, vA23.y, a13);
        a00 = f2fma(p0b, vB01.x, a00);  a10 = f2fma(p1b, vB01.x, a10);
        a01 = f2fma(p0b, vB01.y, a01);  a11 = f2fma(p1b, vB01.y, a11);
        a02 = f2fma(p0b, vB23.x, a02);  a12 = f2fma(p1b, vB23.x, a12);
        a03 = f2fma(p0b, vB23.y, a03);  a13 = f2fma(p1b, vB23.y, a13);
        l0 = f2add(l0, p0a);  l1 = f2add(l1, p1a);
        l0 = f2add(l0, p0b);  l1 = f2add(l1, p1b);
    }
    {
        float le, lo; up2(l0, le, lo);
        float inv = 1.f / (le + lo);
        float e0,o0,e1,o1,e2,o2,e3,o3;
        up2(a00, e0, o0); up2(a01, e1, o1); up2(a02, e2, o2); up2(a03, e3, o3);
        *reinterpret_cast<float4*>(g_AO + ((b * 1024 + qA) * 28 + h * 4)) =
            make_float4((e0+o0)*inv, (e1+o1)*inv, (e2+o2)*inv, (e3+o3)*inv);
    }
    {
        float le, lo; up2(l1, le, lo);
        float inv = 1.f / (le + lo);
        float e0,o0,e1,o1,e2,o2,e3,o3;
        up2(a10, e0, o0); up2(a11, e1, o1); up2(a12, e2, o2); up2(a13, e3, o3);
        *reinterpret_cast<float4*>(g_AO + ((b * 1024 + qA + 128) * 28 + h * 4)) =
            make_float4((e0+o0)*inv, (e1+o1)*inv, (e2+o2)*inv, (e3+o3)*inv);
    }
}

// ---------------------------------------------------------------------------
// K3: LayerNorm(28) + FFN(28->7) + ReLU + residual -> out7 (d_out head),
// then Q2/K2 projections (7->28) into scratch. 1 thread per row.
// ---------------------------------------------------------------------------
__global__ void k_lnffn(const float* __restrict__ x,
                        const float* __restrict__ lnw, const float* __restrict__ lnb,
                        const float* __restrict__ W1,  const float* __restrict__ b1,
                        const float* __restrict__ Wq2, const float* __restrict__ bq2,
                        const float* __restrict__ Wk2, const float* __restrict__ bk2,
                        float* __restrict__ out7) {
    __shared__ float s_lnw[28], s_lnb[28], s_W1[196], s_b1[7];
    __shared__ float s_Wq2[196], s_bq2[28], s_Wk2[196], s_bk2[28];
    int tid = threadIdx.x;
    for (int i = tid; i < 196; i += blockDim.x) { s_W1[i] = W1[i]; s_Wq2[i] = Wq2[i]; s_Wk2[i] = Wk2[i]; }
    if (tid < 28) { s_lnw[tid] = lnw[tid]; s_lnb[tid] = lnb[tid]; s_bq2[tid] = bq2[tid]; s_bk2[tid] = bk2[tid]; }
    if (tid < 7)  { s_b1[tid] = b1[tid]; }
    __syncthreads();

    int r = blockIdx.x * blockDim.x + tid;
    float a[28];
    const float4* ap = reinterpret_cast<const float4*>(g_AO + r * 28);
#pragma unroll
    for (int i = 0; i < 7; i++) {
        float4 t = ap[i];
        a[4*i] = t.x; a[4*i+1] = t.y; a[4*i+2] = t.z; a[4*i+3] = t.w;
    }
    float mu = 0.f;
#pragma unroll
    for (int j = 0; j < 28; j++) mu += a[j];
    mu *= (1.f / 28.f);
    float var = 0.f;
#pragma unroll
    for (int j = 0; j < 28; j++) { float d = a[j] - mu; var += d * d; }
    var *= (1.f / 28.f);
    float rs = rsqrtf(var + 1e-5f);

    float y[28];
#pragma unroll
    for (int j = 0; j < 28; j++) y[j] = (a[j] - mu) * rs * s_lnw[j] + s_lnb[j];

    float z[7];
#pragma unroll
    for (int i = 0; i < 7; i++) {
        float t = s_b1[i];
#pragma unroll
        for (int j = 0; j < 28; j++) t += y[j] * s_W1[j * 7 + i];
        t = fmaxf(t, 0.f) + x[r * 7 + i];
        z[i] = t;
        out7[r * 7 + i] = t;
    }
#pragma unroll
    for (int j = 0; j < 28; j++) {
        float tq = s_bq2[j], tk = s_bk2[j];
#pragma unroll
        for (int i = 0; i < 7; i++) {
            tq += z[i] * s_Wq2[i * 28 + j];
            tk += z[i] * s_Wk2[i * 28 + j];
        }
        g_Q2[r * 28 + j] = tq;
        g_K2[r * 28 + j] = tk;
    }
}

// ---------------------------------------------------------------------------
// K4: second attention weights — K2 in registers, Q2 broadcast from smem,
// two-pass (streamed p + normalize readback), with each 14-FMA dot SPLIT
// into two 7-chains (4 independent chains/thread; crit path halved).
// Block = 512 thr; thread owns adjacent k rows {2m, 2m+1}; STG.64 writes.
// ---------------------------------------------------------------------------
__global__ void __launch_bounds__(512, 1) k_attn2(float* __restrict__ out) {
    __shared__ float sQ[32 * 28];          // q tile (scaled)

    int b = blockIdx.y, tile = blockIdx.x;             // 32 tiles of 32 q rows
    int warp = threadIdx.x >> 5, lane = threadIdx.x & 31;
    const float SC2 = 1.4426950408889634f / 2.6457513110645906f; // log2(e)/sqrt(7)

    for (int t = threadIdx.x; t < 32 * 28; t += 512)
        sQ[t] = g_Q2[(b * 1024 + tile * 32) * 28 + t] * SC2;

    int m = warp * 32 + lane;                           // 0..511
    ulonglong2 kA[7], kB[7];
    {
        const ulonglong2* a = reinterpret_cast<const ulonglong2*>(g_K2 + (b * 1024 + 2 * m) * 28);
        const ulonglong2* c = reinterpret_cast<const ulonglong2*>(g_K2 + (b * 1024 + 2 * m + 1) * 28);
#pragma unroll
        for (int j = 0; j < 7; j++) { kA[j] = a[j]; kB[j] = c[j]; }
    }
    __syncthreads();

    float* obase = out + (b * 1024 + tile * 32) * 1024;

#pragma unroll 4
    for (int q = 0; q < 32; q++) {
        const ulonglong2* qp = reinterpret_cast<const ulonglong2*>(sQ + q * 28);
        ulonglong2 qv[7];
#pragma unroll
        for (int j = 0; j < 7; j++) qv[j] = qp[j];      // broadcast LDS (N=1)

        // split 7+7 chains per dot: 4 independent chains
        u64 aL = f2mul(qv[0].x, kA[0].x);
        u64 aH = f2mul(qv[3].y, kA[3].y);
        u64 bL = f2mul(qv[0].x, kB[0].x);
        u64 bH = f2mul(qv[3].y, kB[3].y);
        aL = f2fma(qv[0].y, kA[0].y, aL);  bL = f2fma(qv[0].y, kB[0].y, bL);
        aH = f2fma(qv[4].x, kA[4].x, aH);  bH = f2fma(qv[4].x, kB[4].x, bH);
        aL = f2fma(qv[1].x, kA[1].x, aL);  bL = f2fma(qv[1].x, kB[1].x, bL);
        aH = f2fma(qv[4].y, kA[4].y, aH);  bH = f2fma(qv[4].y, kB[4].y, bH);
        aL = f2fma(qv[1].y, kA[1].y, aL);  bL = f2fma(qv[1].y, kB[1].y, bL);
        aH = f2fma(qv[5].x, kA[5].x, aH);  bH = f2fma(qv[5].x, kB[5].x, bH);
        aL = f2fma(qv[2].x, kA[2].x, aL);  bL = f2fma(qv[2].x, kB[2].x, bL);
        aH = f2fma(qv[5].y, kA[5].y, aH);  bH = f2fma(qv[5].y, kB[5].y, bH);
        aL = f2fma(qv[2].y, kA[2].y, aL);  bL = f2fma(qv[2].y, kB[2].y, bL);
        aH = f2fma(qv[6].x, kA[6].x, aH);  bH = f2fma(qv[6].x, kB[6].x, bH);
        aL = f2fma(qv[3].x, kA[3].x, aL);  bL = f2fma(qv[3].x, kB[3].x, bL);
        aH = f2fma(qv[6].y, kA[6].y, aH);  bH = f2fma(qv[6].y, kB[6].y, bH);
        u64 accA = f2add(aL, aH);
        u64 accB = f2add(bL, bH);

        float aLo, aHi, bLo, bHi;
        up2(accA, aLo, aHi); up2(accB, bLo, bHi);
        float pA = ex2(aLo + aHi);
        float pB = ex2(bLo + bHi);

        *reinterpret_cast<u64*>(&obase[q * 1024 + 2 * m]) = pk2(pA, pB);
    }
    __syncthreads();   // make all warps' global p-writes visible block-wide

    // Normalize pass: each warp owns q-rows {warp, warp+16}.
#pragma unroll
    for (int rr = 0; rr < 2; rr++) {
        int q = warp + rr * 16;
        float4* row = reinterpret_cast<float4*>(obase + q * 1024);
        float4 v[8];
#pragma unroll
        for (int i = 0; i < 8; i++) v[i] = row[i * 32 + lane];
        float s = 0.f;
#pragma unroll
        for (int i = 0; i < 8; i++) s += (v[i].x + v[i].y) + (v[i].z + v[i].w);
#pragma unroll
        for (int o = 16; o > 0; o >>= 1)
            s += __shfl_xor_sync(0xffffffffu, s, o);
        float iv = 1.f / s;
#pragma unroll
        for (int i = 0; i < 8; i++) {
            v[i].x *= iv; v[i].y *= iv; v[i].z *= iv; v[i].w *= iv;
            row[i * 32 + lane] = v[i];
        }
    }
}

// ---------------------------------------------------------------------------
extern "C" void kernel_launch(void* const* d_in, const int* in_sizes, int n_in,
                              void* d_out, int out_size) {
    const float* x    = (const float*)d_in[0];
    const float* Wq   = (const float*)d_in[1];
    const float* bq   = (const float*)d_in[2];
    const float* Wk   = (const float*)d_in[3];
    const float* bk   = (const float*)d_in[4];
    const float* Wv   = (const float*)d_in[5];
    const float* bv   = (const float*)d_in[6];
    const float* lnw  = (const float*)d_in[7];
    const float* lnb  = (const float*)d_in[8];
    const float* W1   = (const float*)d_in[9];
    const float* b1   = (const float*)d_in[10];
    const float* Wq2  = (const float*)d_in[11];
    const float* bq2  = (const float*)d_in[12];
    const float* Wk2  = (const float*)d_in[13];
    const float* bk2  = (const float*)d_in[14];
    float* out = (float*)d_out;

    k_qkv<<<128, 128>>>(x, Wq, bq, Wk, bk, Wv, bv);
    k_attn1<<<dim3(4, 7, 16), 128>>>();
    k_lnffn<<<128, 128>>>(x, lnw, lnb, W1, b1, Wq2, bq2, Wk2, bk2, out);
    k_attn2<<<dim3(32, 16), 512>>>(out + BB * SS * NIN);
}